// round 11
// baseline (speedup 1.0000x reference)
#include <cuda_runtime.h>
#include <cstdint>

#define Bn 8
#define Sn 1000
#define Cn 512
#define Hn 8
#define Dn 64
#define LAYER 5
#define MTOK (Bn*Sn)          // 8000 tokens
#define KEEP 64               // keys j>=64 contribute < e^-48 relative (ref fp32 underflows them)

// ---------------- scratch (device globals; no allocation allowed) ----------------
__device__ float g_xn[MTOK*Cn];   // layernormed x
__device__ float g_q [MTOK*Cn];
__device__ float g_k [MTOK*Cn];   // only first KEEP rows per batch written/used
__device__ float g_v [MTOK*Cn];
__device__ float g_ctx[MTOK*Cn];

// ---------------- helpers ----------------
__device__ __forceinline__ uint32_t f2tf32(float f) {
    uint32_t u;
    asm("cvt.rna.tf32.f32 %0, %1;" : "=r"(u) : "f"(f));
    return u;
}

__device__ __forceinline__ void mma_tf32(float* c, const uint32_t* a, uint32_t b0, uint32_t b1) {
    asm volatile("mma.sync.aligned.m16n8k8.row.col.f32.tf32.tf32.f32 "
        "{%0,%1,%2,%3}, {%4,%5,%6,%7}, {%8,%9}, {%0,%1,%2,%3};"
        : "+f"(c[0]), "+f"(c[1]), "+f"(c[2]), "+f"(c[3])
        : "r"(a[0]), "r"(a[1]), "r"(a[2]), "r"(a[3]), "r"(b0), "r"(b1));
}

// swizzled word index in a 32-word row (GEMM tiles): granule XOR by row&7
#define GSWZ(r, cp) ((r)*32 + (((((cp) >> 2) ^ ((r) & 7)) & 7) << 2) + ((cp) & 3))
// swizzled word index in a 64-word row (attention tiles)
__device__ __forceinline__ int swz64(int r, int c) {
    return r * 64 + ((c & 3) | ((((c >> 2) ^ (r & 7)) & 15) << 2));
}

// ---------------- layernorm: one block per token ----------------
__global__ void __launch_bounds__(128) k_ln(const float* __restrict__ x,
                                            const float* __restrict__ gw,
                                            const float* __restrict__ bw)
{
    const int row = blockIdx.x;
    const int tid = threadIdx.x;
    float4 v4 = ((const float4*)(x + (size_t)row * Cn))[tid];
    float s  = v4.x + v4.y + v4.z + v4.w;
    float s2 = v4.x*v4.x + v4.y*v4.y + v4.z*v4.z + v4.w*v4.w;
#pragma unroll
    for (int o = 16; o > 0; o >>= 1) {
        s  += __shfl_xor_sync(0xffffffffu, s,  o);
        s2 += __shfl_xor_sync(0xffffffffu, s2, o);
    }
    __shared__ float sh[8];
    if ((tid & 31) == 0) { sh[tid >> 5] = s; sh[4 + (tid >> 5)] = s2; }
    __syncthreads();
    __shared__ float mean_s, inv_s;
    if (tid == 0) {
        float ts  = sh[0] + sh[1] + sh[2] + sh[3];
        float ts2 = sh[4] + sh[5] + sh[6] + sh[7];
        float m   = ts * (1.0f / Cn);
        float var = ts2 * (1.0f / Cn) - m * m;
        mean_s = m;
        inv_s  = rsqrtf(var + 1e-5f);
    }
    __syncthreads();
    const float m = mean_s, inv = inv_s;
    float4 g4 = ((const float4*)gw)[tid];
    float4 b4 = ((const float4*)bw)[tid];
    float4 o4;
    o4.x = (v4.x - m) * inv * g4.x + b4.x;
    o4.y = (v4.y - m) * inv * g4.y + b4.y;
    o4.z = (v4.z - m) * inv * g4.z + b4.z;
    o4.w = (v4.w - m) * inv * g4.w + b4.w;
    ((float4*)(g_xn + (size_t)row * Cn))[tid] = o4;
}

// ---------------- tf32 tensor-core GEMM v3: C[m,n] = sum_k A[m,k]*W[n,k] + bias[n] ----------------
// Tile MT x NT x 32(K), 256 threads = 8 warps (4m x 2n warp grid), dynamic smem double buffer.
// Physical column permutation within each 8-k group: p = ((k&3)<<1)|((k>>2)&1), so the
// fragment pair (k0+tig, k0+tig+4) is ADJACENT -> one LDS.64 per fragment pair.
// XOR-granule swizzle keeps loader stores STS.128 and spreads banks.
template<int MT, int NT>
__device__ __forceinline__ void gemm_body(const float* __restrict__ A,
                                          const float* __restrict__ W,
                                          const float* __restrict__ bias,
                                          float* __restrict__ Cmat,
                                          int m0, int n0, int mlim)
{
    extern __shared__ uint32_t smw[];
    uint32_t* Asm = smw;                  // [2][MT][32]
    uint32_t* Wsm = smw + 2 * MT * 32;    // [2][NT][32]

    const int tid  = threadIdx.x;
    const int warp = tid >> 5, lane = tid & 31;
    const int g    = lane >> 2, tig = lane & 3;
    constexpr int WM = MT / 4, WN = NT / 2;
    constexpr int MI = WM / 16, NI = WN / 8;
    const int wm = (warp & 3) * WM;
    const int wn = (warp >> 2) * WN;

    // loader: row lr (0..31, AI/WI passes), phys granule jg -> logical pair cols
    const int lr  = tid >> 3;
    const int jg  = tid & 7;
    const int klo = (jg >> 1) * 8 + (jg & 1) * 2;   // logical col of (lo.x, lo.y); hi at +4
    constexpr int AI = MT / 32, WI = NT / 32;

    const float* Ap[AI];
#pragma unroll
    for (int i = 0; i < AI; i++) {
        int r = m0 + lr + 32 * i;
        if (r >= mlim) r = mlim - 1;
        Ap[i] = A + (size_t)r * Cn + klo;
    }
    const float* Wp[WI];
#pragma unroll
    for (int i = 0; i < WI; i++)
        Wp[i] = W + (size_t)(n0 + lr + 32 * i) * Cn + klo;

    float2 alo[AI], ahi[AI], wlo[WI], whi[WI];
#pragma unroll
    for (int i = 0; i < AI; i++) { alo[i] = *(const float2*)(Ap[i]); ahi[i] = *(const float2*)(Ap[i] + 4); }
#pragma unroll
    for (int i = 0; i < WI; i++) { wlo[i] = *(const float2*)(Wp[i]); whi[i] = *(const float2*)(Wp[i] + 4); }

    // store chunk 0 into buffer 0; phys order within granule = [lo.x, hi.x, lo.y, hi.y]
#pragma unroll
    for (int i = 0; i < AI; i++) {
        const int r = lr + 32 * i;
        *(uint4*)&Asm[r*32 + (((jg ^ (r & 7)) & 7) << 2)] =
            make_uint4(f2tf32(alo[i].x), f2tf32(ahi[i].x), f2tf32(alo[i].y), f2tf32(ahi[i].y));
    }
#pragma unroll
    for (int i = 0; i < WI; i++) {
        const int r = lr + 32 * i;
        *(uint4*)&Wsm[r*32 + (((jg ^ (r & 7)) & 7) << 2)] =
            make_uint4(f2tf32(wlo[i].x), f2tf32(whi[i].x), f2tf32(wlo[i].y), f2tf32(whi[i].y));
    }
    __syncthreads();

    float acc[MI][NI][4];
#pragma unroll
    for (int mi = 0; mi < MI; mi++)
#pragma unroll
        for (int ni = 0; ni < NI; ni++)
#pragma unroll
            for (int t = 0; t < 4; t++) acc[mi][ni][t] = 0.0f;

    constexpr int NCH = Cn / 32;          // 16
    for (int ch = 0; ch < NCH; ch++) {
        const int boffA = (ch & 1) * MT * 32;
        const int boffW = (ch & 1) * NT * 32;
        if (ch + 1 < NCH) {
            const int k0 = (ch + 1) * 32;
#pragma unroll
            for (int i = 0; i < AI; i++) { alo[i] = *(const float2*)(Ap[i] + k0); ahi[i] = *(const float2*)(Ap[i] + k0 + 4); }
#pragma unroll
            for (int i = 0; i < WI; i++) { wlo[i] = *(const float2*)(Wp[i] + k0); whi[i] = *(const float2*)(Wp[i] + k0 + 4); }
        }
#pragma unroll
        for (int ks = 0; ks < 4; ks++) {
            const int cb = ks * 8 + (tig << 1);      // phys col of fragment pair
            uint32_t a[MI][4];
#pragma unroll
            for (int mi = 0; mi < MI; mi++) {
                const uint2 u0 = *(const uint2*)&Asm[boffA + GSWZ(wm + mi*16 + g,     cb)];
                const uint2 u1 = *(const uint2*)&Asm[boffA + GSWZ(wm + mi*16 + g + 8, cb)];
                a[mi][0] = u0.x; a[mi][1] = u1.x; a[mi][2] = u0.y; a[mi][3] = u1.y;
            }
#pragma unroll
            for (int ni = 0; ni < NI; ni++) {
                const uint2 ub = *(const uint2*)&Wsm[boffW + GSWZ(wn + ni*8 + g, cb)];
#pragma unroll
                for (int mi = 0; mi < MI; mi++)
                    mma_tf32(acc[mi][ni], a[mi], ub.x, ub.y);
            }
        }
        if (ch + 1 < NCH) {
            const int nbA = (~ch & 1) * MT * 32;
            const int nbW = (~ch & 1) * NT * 32;
#pragma unroll
            for (int i = 0; i < AI; i++) {
                const int r = lr + 32 * i;
                *(uint4*)&Asm[nbA + r*32 + (((jg ^ (r & 7)) & 7) << 2)] =
                    make_uint4(f2tf32(alo[i].x), f2tf32(ahi[i].x), f2tf32(alo[i].y), f2tf32(ahi[i].y));
            }
#pragma unroll
            for (int i = 0; i < WI; i++) {
                const int r = lr + 32 * i;
                *(uint4*)&Wsm[nbW + r*32 + (((jg ^ (r & 7)) & 7) << 2)] =
                    make_uint4(f2tf32(wlo[i].x), f2tf32(whi[i].x), f2tf32(wlo[i].y), f2tf32(whi[i].y));
            }
            __syncthreads();
        }
    }

    // epilogue
#pragma unroll
    for (int mi = 0; mi < MI; mi++) {
        const int r = m0 + wm + mi*16 + g;
#pragma unroll
        for (int ni = 0; ni < NI; ni++) {
            const int col = n0 + wn + ni*8 + tig*2;
            const float b0v = bias[col], b1v = bias[col + 1];
            if (r < mlim)
                *(float2*)(Cmat + (size_t)r * Cn + col) =
                    make_float2(acc[mi][ni][0] + b0v, acc[mi][ni][1] + b1v);
            if (r + 8 < mlim)
                *(float2*)(Cmat + (size_t)(r + 8) * Cn + col) =
                    make_float2(acc[mi][ni][2] + b0v, acc[mi][ni][3] + b1v);
        }
    }
}

__global__ void __launch_bounds__(256) k_gemm_q(const float* __restrict__ W,
                                                const float* __restrict__ bias)
{
    gemm_body<128,128>(g_xn, W, bias, g_q, blockIdx.y * 128, blockIdx.x * 128, MTOK);
}

// K/V: only first KEEP=64 tokens of each batch are ever attended to
__global__ void __launch_bounds__(256) k_gemm_kv(const float* __restrict__ Wk_,
                                                 const float* __restrict__ bk_,
                                                 const float* __restrict__ Wv_,
                                                 const float* __restrict__ bv_)
{
    const int m0 = blockIdx.y * Sn;
    if (blockIdx.z == 0) gemm_body<64,128>(g_xn, Wk_, bk_, g_k, m0, blockIdx.x * 128, MTOK);
    else                 gemm_body<64,128>(g_xn, Wv_, bv_, g_v, m0, blockIdx.x * 128, MTOK);
}

__global__ void __launch_bounds__(256) k_gemm_out(const float* __restrict__ W,
                                                  const float* __restrict__ bias,
                                                  float* __restrict__ out)
{
    gemm_body<128,128>(g_ctx, W, bias, out, blockIdx.y * 128, blockIdx.x * 128, MTOK);
}

// ---------------- tensor-core attention (128-query tiles, 256 threads) ----------------
// Per block: one (b,h), 128 queries, 64 keys. Each warp owns 16 q-rows.
// S = Q@K^T (tf32 MMA); branchless p = exp(0.125*s - j) (static-max: score-iq = qk*scale - j,
// iq drops out of softmax); row sums in registers via quad shuffles; P overwrites the warp's
// own Q rows; ctx = P@V with V in natural [key][dim] layout.
// Dynamic smem: QP[128][64] + K[64][64] + V[64][64] = 64KB.
__global__ void __launch_bounds__(256) k_attn()
{
    const int qt  = blockIdx.x;        // 0..7 (128 queries each; last partially valid)
    const int bh  = blockIdx.y;
    const int b   = bh >> 3;
    const int h   = bh & 7;
    const int tid = threadIdx.x;
    const int warp = tid >> 5, lane = tid & 31;
    const int g = lane >> 2, tig = lane & 3;
    const int wm = warp * 16;          // 0..112

    extern __shared__ uint32_t smw[];
    uint32_t* QP = smw;                // [128][64] swizzled; Q then (warp-locally) P
    uint32_t* Ks = smw + 128*64;       // [64][64]
    uint32_t* Vs = smw + 192*64;       // [64][64]

    // cooperative loads
    {
        const int c  = (tid & 15) * 4;
        const int r0 = tid >> 4;       // 0..15
        for (int r = r0; r < 64; r += 16) {
            const size_t kb = ((size_t)(b * Sn + r)) * Cn + h * Dn + c;
            float4 k4 = *(const float4*)(g_k + kb);
            *(uint4*)&Ks[swz64(r, c)] = make_uint4(f2tf32(k4.x), f2tf32(k4.y), f2tf32(k4.z), f2tf32(k4.w));
            float4 v4 = *(const float4*)(g_v + kb);
            *(uint4*)&Vs[swz64(r, c)] = make_uint4(f2tf32(v4.x), f2tf32(v4.y), f2tf32(v4.z), f2tf32(v4.w));
        }
        for (int r = r0; r < 128; r += 16) {
            int qr = qt * 128 + r; if (qr > Sn - 1) qr = Sn - 1;
            float4 q4 = *(const float4*)(g_q + ((size_t)(b * Sn + qr)) * Cn + h * Dn + c);
            *(uint4*)&QP[swz64(r, c)] = make_uint4(f2tf32(q4.x), f2tf32(q4.y), f2tf32(q4.z), f2tf32(q4.w));
        }
    }
    __syncthreads();

    // S = Q @ K^T : warp covers its 16 q-rows x 64 keys (8 n8 tiles), contraction k=64
    float acc[8][4];
#pragma unroll
    for (int ni = 0; ni < 8; ni++)
#pragma unroll
        for (int t = 0; t < 4; t++) acc[ni][t] = 0.0f;

#pragma unroll
    for (int ks = 0; ks < 8; ks++) {
        const int k0 = ks * 8;
        uint32_t a[4];
        a[0] = QP[swz64(wm + g,     k0 + tig)];
        a[1] = QP[swz64(wm + g + 8, k0 + tig)];
        a[2] = QP[swz64(wm + g,     k0 + tig + 4)];
        a[3] = QP[swz64(wm + g + 8, k0 + tig + 4)];
#pragma unroll
        for (int ni = 0; ni < 8; ni++)
            mma_tf32(acc[ni], a, Ks[swz64(ni*8 + g, k0 + tig)], Ks[swz64(ni*8 + g, k0 + tig + 4)]);
    }

    __syncwarp();   // this warp done reading its Q rows before P overwrites them

    // P = exp(0.125*s - j), accumulate row sums, store P (tf32) into the warp's QP rows
    float rs0 = 0.0f, rs1 = 0.0f;
#pragma unroll
    for (int ni = 0; ni < 8; ni++) {
        const float j0 = (float)(ni*8 + 2*tig);
        const float p0 = __expf(fmaf(acc[ni][0], 0.125f, -j0));
        const float p1 = __expf(fmaf(acc[ni][1], 0.125f, -(j0 + 1.0f)));
        const float p2 = __expf(fmaf(acc[ni][2], 0.125f, -j0));
        const float p3 = __expf(fmaf(acc[ni][3], 0.125f, -(j0 + 1.0f)));
        rs0 += p0 + p1;
        rs1 += p2 + p3;
        *(uint2*)&QP[swz64(wm + g,     ni*8 + 2*tig)] = make_uint2(f2tf32(p0), f2tf32(p1));
        *(uint2*)&QP[swz64(wm + g + 8, ni*8 + 2*tig)] = make_uint2(f2tf32(p2), f2tf32(p3));
    }
    rs0 += __shfl_xor_sync(0xffffffffu, rs0, 1);
    rs0 += __shfl_xor_sync(0xffffffffu, rs0, 2);
    rs1 += __shfl_xor_sync(0xffffffffu, rs1, 1);
    rs1 += __shfl_xor_sync(0xffffffffu, rs1, 2);

    __syncwarp();   // P writes visible within the warp

    // ctx = P @ V : A = P [q][key], B = V [key][dim]
    float acc2[8][4];
#pragma unroll
    for (int ni = 0; ni < 8; ni++)
#pragma unroll
        for (int t = 0; t < 4; t++) acc2[ni][t] = 0.0f;

#pragma unroll
    for (int ks = 0; ks < 8; ks++) {
        const int k0 = ks * 8;
        uint32_t a[4];
        a[0] = QP[swz64(wm + g,     k0 + tig)];
        a[1] = QP[swz64(wm + g + 8, k0 + tig)];
        a[2] = QP[swz64(wm + g,     k0 + tig + 4)];
        a[3] = QP[swz64(wm + g + 8, k0 + tig + 4)];
#pragma unroll
        for (int ni = 0; ni < 8; ni++)
            mma_tf32(acc2[ni], a, Vs[swz64(k0 + tig, ni*8 + g)], Vs[swz64(k0 + tig + 4, ni*8 + g)]);
    }

    // epilogue: normalize and write
    const int   q0  = qt * 128 + wm + g;
    const int   q1  = q0 + 8;
    const float il0 = 1.0f / rs0;
    const float il1 = 1.0f / rs1;
#pragma unroll
    for (int ni = 0; ni < 8; ni++) {
        const int d = ni*8 + 2*tig;
        if (q0 < Sn)
            *(float2*)(g_ctx + ((size_t)(b * Sn + q0)) * Cn + h * Dn + d) =
                make_float2(acc2[ni][0] * il0, acc2[ni][1] * il0);
        if (q1 < Sn)
            *(float2*)(g_ctx + ((size_t)(b * Sn + q1)) * Cn + h * Dn + d) =
                make_float2(acc2[ni][2] * il1, acc2[ni][3] * il1);
    }
}

// ---------------- launch ----------------
extern "C" void kernel_launch(void* const* d_in, const int* in_sizes, int n_in,
                              void* d_out, int out_size)
{
    const float* x   = (const float*)d_in[0];
    const float* lng = (const float*)d_in[1] + LAYER * Cn;
    const float* lnb = (const float*)d_in[2] + LAYER * Cn;
    const float* Wq  = (const float*)d_in[3] + (size_t)LAYER * Cn * Cn;
    const float* bq  = (const float*)d_in[4] + LAYER * Cn;
    const float* Wk  = (const float*)d_in[5] + (size_t)LAYER * Cn * Cn;
    const float* bk  = (const float*)d_in[6] + LAYER * Cn;
    const float* Wv  = (const float*)d_in[7] + (size_t)LAYER * Cn * Cn;
    const float* bv  = (const float*)d_in[8] + LAYER * Cn;
    const float* Wo  = (const float*)d_in[9] + (size_t)LAYER * Cn * Cn;
    const float* bo  = (const float*)d_in[10] + LAYER * Cn;
    float* out = (float*)d_out;

    const int smem_g128 = 2 * (128 + 128) * 32 * 4;   // 65536
    const int smem_g64  = 2 * (64 + 128) * 32 * 4;    // 49152
    const int smem_attn = 256 * 64 * 4;               // 65536

    cudaFuncSetAttribute(k_gemm_q,   cudaFuncAttributeMaxDynamicSharedMemorySize, smem_g128);
    cudaFuncSetAttribute(k_gemm_kv,  cudaFuncAttributeMaxDynamicSharedMemorySize, smem_g64);
    cudaFuncSetAttribute(k_gemm_out, cudaFuncAttributeMaxDynamicSharedMemorySize, smem_g128);
    cudaFuncSetAttribute(k_attn,     cudaFuncAttributeMaxDynamicSharedMemorySize, smem_attn);

    k_ln      <<<MTOK, 128>>>(x, lng, lnb);
    k_gemm_q  <<<dim3(4, 63),   256, smem_g128>>>(Wq, bq);
    k_gemm_kv <<<dim3(4, Bn, 2), 256, smem_g64>>>(Wk, bk, Wv, bv);
    k_attn    <<<dim3(8, 64),   256, smem_attn>>>();
    k_gemm_out<<<dim3(4, 63),   256, smem_g128>>>(Wo, bo, out);
}

// round 13
// speedup vs baseline: 1.1564x; 1.1564x over previous
#include <cuda_runtime.h>
#include <cstdint>

#define Bn 8
#define Sn 1000
#define Cn 512
#define Hn 8
#define Dn 64
#define LAYER 5
#define MTOK (Bn*Sn)          // 8000 tokens
#define KEEP 64               // keys j>=64 contribute < e^-48 relative (ref fp32 underflows them)

// ---------------- scratch (device globals; no allocation allowed) ----------------
__device__ float g_xn[MTOK*Cn];   // layernormed x, tf32-rounded
__device__ float g_q [MTOK*Cn];   // tf32-rounded
__device__ float g_k [MTOK*Cn];   // tf32-rounded; only first KEEP rows per batch used
__device__ float g_v [MTOK*Cn];   // tf32-rounded
__device__ float g_ctx[MTOK*Cn];  // tf32-rounded
__device__ float g_wq[Cn*Cn];     // tf32-rounded weights
__device__ float g_wk[Cn*Cn];
__device__ float g_wv[Cn*Cn];
__device__ float g_wo[Cn*Cn];

// ---------------- helpers ----------------
__device__ __forceinline__ uint32_t f2tf32(float f) {
    uint32_t u;
    asm("cvt.rna.tf32.f32 %0, %1;" : "=r"(u) : "f"(f));
    return u;
}
__device__ __forceinline__ float rnd_tf32(float f) { return __uint_as_float(f2tf32(f)); }

__device__ __forceinline__ void mma_tf32(float* c, const uint32_t* a, uint32_t b0, uint32_t b1) {
    asm volatile("mma.sync.aligned.m16n8k8.row.col.f32.tf32.tf32.f32 "
        "{%0,%1,%2,%3}, {%4,%5,%6,%7}, {%8,%9}, {%0,%1,%2,%3};"
        : "+f"(c[0]), "+f"(c[1]), "+f"(c[2]), "+f"(c[3])
        : "r"(a[0]), "r"(a[1]), "r"(a[2]), "r"(a[3]), "r"(b0), "r"(b1));
}

// swizzled word index in a 64-word row (attention tiles)
__device__ __forceinline__ int swz64(int r, int c) {
    return r * 64 + ((c & 3) | ((((c >> 2) ^ (r & 7)) & 15) << 2));
}

// ---------------- weight prep: round 4 weight matrices to tf32 once ----------------
__global__ void __launch_bounds__(256) k_prep(const float* __restrict__ W0,
                                              const float* __restrict__ W1,
                                              const float* __restrict__ W2,
                                              const float* __restrict__ W3)
{
    const int m = blockIdx.y;
    const int i = blockIdx.x * 256 + threadIdx.x;   // float4 index, [0, Cn*Cn/4)
    const float* src; float* dst;
    if      (m == 0) { src = W0; dst = g_wq; }
    else if (m == 1) { src = W1; dst = g_wk; }
    else if (m == 2) { src = W2; dst = g_wv; }
    else             { src = W3; dst = g_wo; }
    float4 v = ((const float4*)src)[i];
    ((uint4*)dst)[i] = make_uint4(f2tf32(v.x), f2tf32(v.y), f2tf32(v.z), f2tf32(v.w));
}

// ---------------- layernorm: one block per token; output tf32-rounded ----------------
__global__ void __launch_bounds__(128) k_ln(const float* __restrict__ x,
                                            const float* __restrict__ gw,
                                            const float* __restrict__ bw)
{
    const int row = blockIdx.x;
    const int tid = threadIdx.x;
    float4 v4 = ((const float4*)(x + (size_t)row * Cn))[tid];
    float s  = v4.x + v4.y + v4.z + v4.w;
    float s2 = v4.x*v4.x + v4.y*v4.y + v4.z*v4.z + v4.w*v4.w;
#pragma unroll
    for (int o = 16; o > 0; o >>= 1) {
        s  += __shfl_xor_sync(0xffffffffu, s,  o);
        s2 += __shfl_xor_sync(0xffffffffu, s2, o);
    }
    __shared__ float sh[8];
    if ((tid & 31) == 0) { sh[tid >> 5] = s; sh[4 + (tid >> 5)] = s2; }
    __syncthreads();
    __shared__ float mean_s, inv_s;
    if (tid == 0) {
        float ts  = sh[0] + sh[1] + sh[2] + sh[3];
        float ts2 = sh[4] + sh[5] + sh[6] + sh[7];
        float m   = ts * (1.0f / Cn);
        float var = ts2 * (1.0f / Cn) - m * m;
        mean_s = m;
        inv_s  = rsqrtf(var + 1e-5f);
    }
    __syncthreads();
    const float m = mean_s, inv = inv_s;
    float4 g4 = ((const float4*)gw)[tid];
    float4 b4 = ((const float4*)bw)[tid];
    uint4 o4;
    o4.x = f2tf32((v4.x - m) * inv * g4.x + b4.x);
    o4.y = f2tf32((v4.y - m) * inv * g4.y + b4.y);
    o4.z = f2tf32((v4.z - m) * inv * g4.z + b4.z);
    o4.w = f2tf32((v4.w - m) * inv * g4.w + b4.w);
    ((uint4*)(g_xn + (size_t)row * Cn))[tid] = o4;
}

// ---------------- tf32 tensor-core GEMM (R7-proven v2, cvt-free loader) ----------------
// C[m,n] = sum_k A[m,k]*W[n,k] + bias[n]. A and W hold pre-rounded tf32 bits.
// Tile MT x NT x 16(K), 256 threads = 8 warps (4m x 2n), double-buffered static smem,
// one __syncthreads per k-chunk. RND: round outputs to tf32 (for q/k/v feeding attn).
template<int MT, int NT, bool RND>
__device__ __forceinline__ void gemm_body(const float* __restrict__ A,
                                          const float* __restrict__ W,
                                          const float* __restrict__ bias,
                                          float* __restrict__ Cmat,
                                          int m0, int n0, int mlim)
{
    constexpr int KC  = 16;
    constexpr int PAD = 20;                // 16 cols written, pad to 20
    __shared__ uint32_t Asm[2][MT][PAD];
    __shared__ uint32_t Wsm[2][NT][PAD];

    const int tid  = threadIdx.x;
    const int warp = tid >> 5, lane = tid & 31;
    const int g    = lane >> 2, tig = lane & 3;
    constexpr int WM = MT / 4, WN = NT / 2;
    constexpr int MI = WM / 16, NI = WN / 8;
    const int wm = (warp & 3) * WM;
    const int wn = (warp >> 2) * WN;

    const int lr = tid >> 2;              // 0..63
    const int lc = (tid & 3) * 4;         // 0,4,8,12
    constexpr int AI = MT / 64;
    constexpr int WI = NT / 64;

    const float* Ap[AI];
#pragma unroll
    for (int i = 0; i < AI; i++) {
        int r = m0 + lr + 64 * i;
        if (r >= mlim) r = mlim - 1;
        Ap[i] = A + (size_t)r * Cn + lc;
    }
    const float* Wp[WI];
#pragma unroll
    for (int i = 0; i < WI; i++)
        Wp[i] = W + (size_t)(n0 + lr + 64 * i) * Cn + lc;

    uint4 abuf[AI], wbuf[WI];
#pragma unroll
    for (int i = 0; i < AI; i++) abuf[i] = *(const uint4*)(Ap[i]);
#pragma unroll
    for (int i = 0; i < WI; i++) wbuf[i] = *(const uint4*)(Wp[i]);
#pragma unroll
    for (int i = 0; i < AI; i++) *(uint4*)&Asm[0][lr + 64*i][lc] = abuf[i];
#pragma unroll
    for (int i = 0; i < WI; i++) *(uint4*)&Wsm[0][lr + 64*i][lc] = wbuf[i];
    __syncthreads();

    float acc[MI][NI][4];
#pragma unroll
    for (int mi = 0; mi < MI; mi++)
#pragma unroll
        for (int ni = 0; ni < NI; ni++)
#pragma unroll
            for (int t = 0; t < 4; t++) acc[mi][ni][t] = 0.0f;

    constexpr int NCH = Cn / KC;          // 32
    for (int ch = 0; ch < NCH; ch++) {
        const int buf = ch & 1;
        if (ch + 1 < NCH) {
            const int k0 = (ch + 1) * KC;
#pragma unroll
            for (int i = 0; i < AI; i++) abuf[i] = *(const uint4*)(Ap[i] + k0);
#pragma unroll
            for (int i = 0; i < WI; i++) wbuf[i] = *(const uint4*)(Wp[i] + k0);
        }
#pragma unroll
        for (int ks = 0; ks < KC / 8; ks++) {
            const int k0 = ks * 8;
            uint32_t a[MI][4];
#pragma unroll
            for (int mi = 0; mi < MI; mi++) {
                a[mi][0] = Asm[buf][wm + mi*16 + g    ][k0 + tig];
                a[mi][1] = Asm[buf][wm + mi*16 + g + 8][k0 + tig];
                a[mi][2] = Asm[buf][wm + mi*16 + g    ][k0 + tig + 4];
                a[mi][3] = Asm[buf][wm + mi*16 + g + 8][k0 + tig + 4];
            }
#pragma unroll
            for (int ni = 0; ni < NI; ni++) {
                const uint32_t b0 = Wsm[buf][wn + ni*8 + g][k0 + tig];
                const uint32_t b1 = Wsm[buf][wn + ni*8 + g][k0 + tig + 4];
#pragma unroll
                for (int mi = 0; mi < MI; mi++)
                    mma_tf32(acc[mi][ni], a[mi], b0, b1);
            }
        }
        if (ch + 1 < NCH) {
            const int nb = buf ^ 1;
#pragma unroll
            for (int i = 0; i < AI; i++) *(uint4*)&Asm[nb][lr + 64*i][lc] = abuf[i];
#pragma unroll
            for (int i = 0; i < WI; i++) *(uint4*)&Wsm[nb][lr + 64*i][lc] = wbuf[i];
            __syncthreads();
        }
    }

    // epilogue (optionally tf32-rounded outputs)
#pragma unroll
    for (int mi = 0; mi < MI; mi++) {
        const int r = m0 + wm + mi*16 + g;
#pragma unroll
        for (int ni = 0; ni < NI; ni++) {
            const int col = n0 + wn + ni*8 + tig*2;
            const float b0v = bias[col], b1v = bias[col + 1];
            float c0 = acc[mi][ni][0] + b0v, c1 = acc[mi][ni][1] + b1v;
            float c2 = acc[mi][ni][2] + b0v, c3 = acc[mi][ni][3] + b1v;
            if (RND) {
                c0 = rnd_tf32(c0); c1 = rnd_tf32(c1);
                c2 = rnd_tf32(c2); c3 = rnd_tf32(c3);
            }
            if (r < mlim)
                *(float2*)(Cmat + (size_t)r * Cn + col) = make_float2(c0, c1);
            if (r + 8 < mlim)
                *(float2*)(Cmat + (size_t)(r + 8) * Cn + col) = make_float2(c2, c3);
        }
    }
}

__global__ void __launch_bounds__(256) k_gemm_q(const float* __restrict__ bias)
{
    gemm_body<128,128,true>(g_xn, g_wq, bias, g_q, blockIdx.y * 128, blockIdx.x * 128, MTOK);
}

// K/V: only first KEEP=64 tokens of each batch are ever attended to
__global__ void __launch_bounds__(256) k_gemm_kv(const float* __restrict__ bk_,
                                                 const float* __restrict__ bv_)
{
    const int m0 = blockIdx.y * Sn;
    if (blockIdx.z == 0) gemm_body<64,128,true>(g_xn, g_wk, bk_, g_k, m0, blockIdx.x * 128, MTOK);
    else                 gemm_body<64,128,true>(g_xn, g_wv, bv_, g_v, m0, blockIdx.x * 128, MTOK);
}

__global__ void __launch_bounds__(256) k_gemm_out(const float* __restrict__ bias,
                                                  float* __restrict__ out)
{
    gemm_body<128,128,false>(g_ctx, g_wo, bias, out, blockIdx.y * 128, blockIdx.x * 128, MTOK);
}

// ---------------- tensor-core attention (R7-proven, cvt-free loads) ----------------
// Per block: one (b,h), 64 queries, 64 keys. S = Q@K^T (tf32 MMA);
// branchless p = exp(0.125*s - j) (static-max: score-iq = qk*scale - j, iq drops out
// of softmax); row sums in registers via quad shuffles (summing the tf32-rounded p for
// consistency with the stored P); P overwrites the warp's own Q rows; ctx = P@V with V
// in natural [key][dim] layout. Inputs are pre-rounded tf32 bits -> raw uint4 loads.
__global__ void __launch_bounds__(128) k_attn()
{
    const int qt  = blockIdx.x;        // 0..15 (64 queries each; last partially valid)
    const int bh  = blockIdx.y;
    const int b   = bh >> 3;
    const int h   = bh & 7;
    const int tid = threadIdx.x;
    const int warp = tid >> 5, lane = tid & 31;
    const int g = lane >> 2, tig = lane & 3;
    const int wm = warp * 16;

    __shared__ uint32_t Qs[64*64];     // [q][dim] tf32 bits; later reused as P [q][key]
    __shared__ uint32_t Ks[64*64];     // [key][dim]
    __shared__ uint32_t Vs[64*64];     // [key][dim]

    // cooperative loads (raw tf32 bits, swizzled uint4 stores)
    {
        const int c  = (tid & 15) * 4;
        const int r0 = tid >> 4;
        for (int r = r0; r < 64; r += 8) {
            const size_t kb = ((size_t)(b * Sn + r)) * Cn + h * Dn + c;
            *(uint4*)&Ks[swz64(r, c)] = *(const uint4*)(g_k + kb);
            *(uint4*)&Vs[swz64(r, c)] = *(const uint4*)(g_v + kb);
            int qr = qt * 64 + r; if (qr > Sn - 1) qr = Sn - 1;
            *(uint4*)&Qs[swz64(r, c)] = *(const uint4*)(g_q + ((size_t)(b * Sn + qr)) * Cn + h * Dn + c);
        }
    }
    __syncthreads();

    // S = Q @ K^T : warp covers 16 q-rows x 64 keys (8 n8 tiles), contraction k=64
    float acc[8][4];
#pragma unroll
    for (int ni = 0; ni < 8; ni++)
#pragma unroll
        for (int t = 0; t < 4; t++) acc[ni][t] = 0.0f;

#pragma unroll
    for (int ks = 0; ks < 8; ks++) {
        const int k0 = ks * 8;
        uint32_t a[4];
        a[0] = Qs[swz64(wm + g,     k0 + tig)];
        a[1] = Qs[swz64(wm + g + 8, k0 + tig)];
        a[2] = Qs[swz64(wm + g,     k0 + tig + 4)];
        a[3] = Qs[swz64(wm + g + 8, k0 + tig + 4)];
#pragma unroll
        for (int ni = 0; ni < 8; ni++)
            mma_tf32(acc[ni], a, Ks[swz64(ni*8 + g, k0 + tig)], Ks[swz64(ni*8 + g, k0 + tig + 4)]);
    }

    __syncwarp();   // all lanes done reading this warp's Q rows before P overwrites them

    // P = exp(0.125*s - j) rounded to tf32; row sums over the rounded values
    float rs0 = 0.0f, rs1 = 0.0f;
#pragma unroll
    for (int ni = 0; ni < 8; ni++) {
        const float j0 = (float)(ni*8 + 2*tig);
        const float p0 = rnd_tf32(__expf(fmaf(acc[ni][0], 0.125f, -j0)));
        const float p1 = rnd_tf32(__expf(fmaf(acc[ni][1], 0.125f, -(j0 + 1.0f))));
        const float p2 = rnd_tf32(__expf(fmaf(acc[ni][2], 0.125f, -j0)));
        const float p3 = rnd_tf32(__expf(fmaf(acc[ni][3], 0.125f, -(j0 + 1.0f))));
        rs0 += p0 + p1;
        rs1 += p2 + p3;
        *(uint2*)&Qs[swz64(wm + g,     ni*8 + 2*tig)] = make_uint2(__float_as_uint(p0), __float_as_uint(p1));
        *(uint2*)&Qs[swz64(wm + g + 8, ni*8 + 2*tig)] = make_uint2(__float_as_uint(p2), __float_as_uint(p3));
    }
    rs0 += __shfl_xor_sync(0xffffffffu, rs0, 1);
    rs0 += __shfl_xor_sync(0xffffffffu, rs0, 2);
    rs1 += __shfl_xor_sync(0xffffffffu, rs1, 1);
    rs1 += __shfl_xor_sync(0xffffffffu, rs1, 2);

    __syncwarp();   // P writes visible within the warp

    // ctx = P @ V : A = P [q][key], B = V [key][dim]
    float acc2[8][4];
#pragma unroll
    for (int ni = 0; ni < 8; ni++)
#pragma unroll
        for (int t = 0; t < 4; t++) acc2[ni][t] = 0.0f;

#pragma unroll
    for (int ks = 0; ks < 8; ks++) {
        const int k0 = ks * 8;
        uint32_t a[4];
        a[0] = Qs[swz64(wm + g,     k0 + tig)];
        a[1] = Qs[swz64(wm + g + 8, k0 + tig)];
        a[2] = Qs[swz64(wm + g,     k0 + tig + 4)];
        a[3] = Qs[swz64(wm + g + 8, k0 + tig + 4)];
#pragma unroll
        for (int ni = 0; ni < 8; ni++)
            mma_tf32(acc2[ni], a, Vs[swz64(k0 + tig, ni*8 + g)], Vs[swz64(k0 + tig + 4, ni*8 + g)]);
    }

    // epilogue: normalize, round to tf32 (feeds the out-GEMM raw), write
    const int   q0  = qt * 64 + wm + g;
    const int   q1  = q0 + 8;
    const float il0 = 1.0f / rs0;
    const float il1 = 1.0f / rs1;
#pragma unroll
    for (int ni = 0; ni < 8; ni++) {
        const int d = ni*8 + 2*tig;
        if (q0 < Sn)
            *(float2*)(g_ctx + ((size_t)(b * Sn + q0)) * Cn + h * Dn + d) =
                make_float2(rnd_tf32(acc2[ni][0] * il0), rnd_tf32(acc2[ni][1] * il0));
        if (q1 < Sn)
            *(float2*)(g_ctx + ((size_t)(b * Sn + q1)) * Cn + h * Dn + d) =
                make_float2(rnd_tf32(acc2[ni][2] * il1), rnd_tf32(acc2[ni][3] * il1));
    }
}

// ---------------- launch ----------------
extern "C" void kernel_launch(void* const* d_in, const int* in_sizes, int n_in,
                              void* d_out, int out_size)
{
    const float* x   = (const float*)d_in[0];
    const float* lng = (const float*)d_in[1] + LAYER * Cn;
    const float* lnb = (const float*)d_in[2] + LAYER * Cn;
    const float* Wq  = (const float*)d_in[3] + (size_t)LAYER * Cn * Cn;
    const float* bq  = (const float*)d_in[4] + LAYER * Cn;
    const float* Wk  = (const float*)d_in[5] + (size_t)LAYER * Cn * Cn;
    const float* bk  = (const float*)d_in[6] + LAYER * Cn;
    const float* Wv  = (const float*)d_in[7] + (size_t)LAYER * Cn * Cn;
    const float* bv  = (const float*)d_in[8] + LAYER * Cn;
    const float* Wo  = (const float*)d_in[9] + (size_t)LAYER * Cn * Cn;
    const float* bo  = (const float*)d_in[10] + LAYER * Cn;
    float* out = (float*)d_out;

    k_prep    <<<dim3(Cn*Cn/1024, 4), 256>>>(Wq, Wk, Wv, Wo);
    k_ln      <<<MTOK, 128>>>(x, lng, lnb);
    k_gemm_q  <<<dim3(4, 63), 256>>>(bq);
    k_gemm_kv <<<dim3(4, Bn, 2), 256>>>(bk, bv);
    k_attn    <<<dim3(16, 64), 128>>>();
    k_gemm_out<<<dim3(4, 63), 256>>>(bo, out);
}

// round 14
// speedup vs baseline: 1.3102x; 1.1330x over previous
#include <cuda_runtime.h>
#include <cstdint>

#define Bn 8
#define Sn 1000
#define Cn 512
#define Hn 8
#define Dn 64
#define LAYER 5
#define MTOK (Bn*Sn)          // 8000 tokens
#define KEEP 64               // keys j>=64 contribute < e^-48 relative (ref fp32 underflows them)

// ---------------- scratch (device globals; no allocation allowed) ----------------
__device__ float g_xn[MTOK*Cn];   // layernormed x, tf32-rounded
__device__ float g_q [MTOK*Cn];   // tf32-rounded
__device__ float g_k [MTOK*Cn];   // tf32-rounded; only first KEEP rows per batch used
__device__ float g_v [MTOK*Cn];   // tf32-rounded
__device__ float g_ctx[MTOK*Cn];  // tf32-rounded
__device__ float g_wq[Cn*Cn];     // tf32-rounded weights
__device__ float g_wk[Cn*Cn];
__device__ float g_wv[Cn*Cn];
__device__ float g_wo[Cn*Cn];

// ---------------- helpers ----------------
__device__ __forceinline__ uint32_t f2tf32(float f) {
    uint32_t u;
    asm("cvt.rna.tf32.f32 %0, %1;" : "=r"(u) : "f"(f));
    return u;
}
__device__ __forceinline__ float rnd_tf32(float f) { return __uint_as_float(f2tf32(f)); }

__device__ __forceinline__ void mma_tf32(float* c, const uint32_t* a, uint32_t b0, uint32_t b1) {
    asm volatile("mma.sync.aligned.m16n8k8.row.col.f32.tf32.tf32.f32 "
        "{%0,%1,%2,%3}, {%4,%5,%6,%7}, {%8,%9}, {%0,%1,%2,%3};"
        : "+f"(c[0]), "+f"(c[1]), "+f"(c[2]), "+f"(c[3])
        : "r"(a[0]), "r"(a[1]), "r"(a[2]), "r"(a[3]), "r"(b0), "r"(b1));
}

// swizzled word index in a 64-word row (attention tiles)
__device__ __forceinline__ int swz64(int r, int c) {
    return r * 64 + ((c & 3) | ((((c >> 2) ^ (r & 7)) & 15) << 2));
}

// ---------------- fused LN + weight-prep (independent, memory-bound) ----------------
// blocks [0, 4000): layernorm, 2 rows per block (256 threads = 2 x 128)
// blocks [4000, 5024): tf32-round the 4 weight matrices (256 float4 each)
#define LN_BLOCKS (MTOK/2)
__global__ void __launch_bounds__(256) k_pre(const float* __restrict__ x,
                                             const float* __restrict__ gw,
                                             const float* __restrict__ bw,
                                             const float* __restrict__ W0,
                                             const float* __restrict__ W1,
                                             const float* __restrict__ W2,
                                             const float* __restrict__ W3)
{
    const int bid = blockIdx.x;
    const int tid = threadIdx.x;
    if (bid < LN_BLOCKS) {
        const int sub = tid >> 7;          // 0..1 : which row
        const int t   = tid & 127;
        const int row = bid * 2 + sub;
        float4 v4 = ((const float4*)(x + (size_t)row * Cn))[t];
        float s  = v4.x + v4.y + v4.z + v4.w;
        float s2 = v4.x*v4.x + v4.y*v4.y + v4.z*v4.z + v4.w*v4.w;
#pragma unroll
        for (int o = 16; o > 0; o >>= 1) {
            s  += __shfl_xor_sync(0xffffffffu, s,  o);
            s2 += __shfl_xor_sync(0xffffffffu, s2, o);
        }
        __shared__ float sh[2][8];
        __shared__ float ms[2], is[2];
        if ((t & 31) == 0) { sh[sub][t >> 5] = s; sh[sub][4 + (t >> 5)] = s2; }
        __syncthreads();
        if (t == 0) {
            float ts  = sh[sub][0] + sh[sub][1] + sh[sub][2] + sh[sub][3];
            float ts2 = sh[sub][4] + sh[sub][5] + sh[sub][6] + sh[sub][7];
            float m   = ts * (1.0f / Cn);
            float var = ts2 * (1.0f / Cn) - m * m;
            ms[sub] = m;
            is[sub] = rsqrtf(var + 1e-5f);
        }
        __syncthreads();
        const float m = ms[sub], inv = is[sub];
        float4 g4 = ((const float4*)gw)[t];
        float4 b4 = ((const float4*)bw)[t];
        uint4 o4;
        o4.x = f2tf32((v4.x - m) * inv * g4.x + b4.x);
        o4.y = f2tf32((v4.y - m) * inv * g4.y + b4.y);
        o4.z = f2tf32((v4.z - m) * inv * g4.z + b4.z);
        o4.w = f2tf32((v4.w - m) * inv * g4.w + b4.w);
        ((uint4*)(g_xn + (size_t)row * Cn))[t] = o4;
    } else {
        const int pb = bid - LN_BLOCKS;         // 0..1023; 256 blocks per matrix
        const int m  = pb >> 8;
        const int i  = (pb & 255) * 256 + tid;  // float4 index in [0, Cn*Cn/4)
        const float* src; float* dst;
        if      (m == 0) { src = W0; dst = g_wq; }
        else if (m == 1) { src = W1; dst = g_wk; }
        else if (m == 2) { src = W2; dst = g_wv; }
        else             { src = W3; dst = g_wo; }
        float4 v = ((const float4*)src)[i];
        ((uint4*)dst)[i] = make_uint4(f2tf32(v.x), f2tf32(v.y), f2tf32(v.z), f2tf32(v.w));
    }
}

// ---------------- tf32 tensor-core GEMM (R7-proven v2; dynamic smem) ----------------
// C[m,n] = sum_k A[m,k]*W[n,k] + bias[n]. A and W hold pre-rounded tf32 bits.
// Tile MT x NT x 16(K), 256 threads = 8 warps (4m x 2n), double-buffered smem,
// one __syncthreads per k-chunk. RND: round outputs to tf32 (for q/k/v feeding attn).
template<int MT, int NT, bool RND>
__device__ __forceinline__ void gemm_body(const float* __restrict__ A,
                                          const float* __restrict__ W,
                                          const float* __restrict__ bias,
                                          float* __restrict__ Cmat,
                                          int m0, int n0, int mlim)
{
    constexpr int KC  = 16;
    constexpr int PAD = 20;                // 16 cols written, pad to 20
    extern __shared__ uint32_t smw[];
    uint32_t (*Asm)[MT][PAD] = (uint32_t(*)[MT][PAD])smw;                 // [2][MT][PAD]
    uint32_t (*Wsm)[NT][PAD] = (uint32_t(*)[NT][PAD])(smw + 2*MT*PAD);    // [2][NT][PAD]

    const int tid  = threadIdx.x;
    const int warp = tid >> 5, lane = tid & 31;
    const int g    = lane >> 2, tig = lane & 3;
    constexpr int WM = MT / 4, WN = NT / 2;
    constexpr int MI = WM / 16, NI = WN / 8;
    const int wm = (warp & 3) * WM;
    const int wn = (warp >> 2) * WN;

    const int lr = tid >> 2;              // 0..63
    const int lc = (tid & 3) * 4;         // 0,4,8,12
    constexpr int AI = MT / 64;
    constexpr int WI = NT / 64;

    const float* Ap[AI];
#pragma unroll
    for (int i = 0; i < AI; i++) {
        int r = m0 + lr + 64 * i;
        if (r >= mlim) r = mlim - 1;
        Ap[i] = A + (size_t)r * Cn + lc;
    }
    const float* Wp[WI];
#pragma unroll
    for (int i = 0; i < WI; i++)
        Wp[i] = W + (size_t)(n0 + lr + 64 * i) * Cn + lc;

    uint4 abuf[AI], wbuf[WI];
#pragma unroll
    for (int i = 0; i < AI; i++) abuf[i] = *(const uint4*)(Ap[i]);
#pragma unroll
    for (int i = 0; i < WI; i++) wbuf[i] = *(const uint4*)(Wp[i]);
#pragma unroll
    for (int i = 0; i < AI; i++) *(uint4*)&Asm[0][lr + 64*i][lc] = abuf[i];
#pragma unroll
    for (int i = 0; i < WI; i++) *(uint4*)&Wsm[0][lr + 64*i][lc] = wbuf[i];
    __syncthreads();

    float acc[MI][NI][4];
#pragma unroll
    for (int mi = 0; mi < MI; mi++)
#pragma unroll
        for (int ni = 0; ni < NI; ni++)
#pragma unroll
            for (int t = 0; t < 4; t++) acc[mi][ni][t] = 0.0f;

    constexpr int NCH = Cn / KC;          // 32
    for (int ch = 0; ch < NCH; ch++) {
        const int buf = ch & 1;
        if (ch + 1 < NCH) {
            const int k0 = (ch + 1) * KC;
#pragma unroll
            for (int i = 0; i < AI; i++) abuf[i] = *(const uint4*)(Ap[i] + k0);
#pragma unroll
            for (int i = 0; i < WI; i++) wbuf[i] = *(const uint4*)(Wp[i] + k0);
        }
#pragma unroll
        for (int ks = 0; ks < KC / 8; ks++) {
            const int k0 = ks * 8;
            uint32_t a[MI][4];
#pragma unroll
            for (int mi = 0; mi < MI; mi++) {
                a[mi][0] = Asm[buf][wm + mi*16 + g    ][k0 + tig];
                a[mi][1] = Asm[buf][wm + mi*16 + g + 8][k0 + tig];
                a[mi][2] = Asm[buf][wm + mi*16 + g    ][k0 + tig + 4];
                a[mi][3] = Asm[buf][wm + mi*16 + g + 8][k0 + tig + 4];
            }
#pragma unroll
            for (int ni = 0; ni < NI; ni++) {
                const uint32_t b0 = Wsm[buf][wn + ni*8 + g][k0 + tig];
                const uint32_t b1 = Wsm[buf][wn + ni*8 + g][k0 + tig + 4];
#pragma unroll
                for (int mi = 0; mi < MI; mi++)
                    mma_tf32(acc[mi][ni], a[mi], b0, b1);
            }
        }
        if (ch + 1 < NCH) {
            const int nb = buf ^ 1;
#pragma unroll
            for (int i = 0; i < AI; i++) *(uint4*)&Asm[nb][lr + 64*i][lc] = abuf[i];
#pragma unroll
            for (int i = 0; i < WI; i++) *(uint4*)&Wsm[nb][lr + 64*i][lc] = wbuf[i];
            __syncthreads();
        }
    }

    // epilogue (optionally tf32-rounded outputs)
#pragma unroll
    for (int mi = 0; mi < MI; mi++) {
        const int r = m0 + wm + mi*16 + g;
#pragma unroll
        for (int ni = 0; ni < NI; ni++) {
            const int col = n0 + wn + ni*8 + tig*2;
            const float b0v = bias[col], b1v = bias[col + 1];
            float c0 = acc[mi][ni][0] + b0v, c1 = acc[mi][ni][1] + b1v;
            float c2 = acc[mi][ni][2] + b0v, c3 = acc[mi][ni][3] + b1v;
            if (RND) {
                c0 = rnd_tf32(c0); c1 = rnd_tf32(c1);
                c2 = rnd_tf32(c2); c3 = rnd_tf32(c3);
            }
            if (r < mlim)
                *(float2*)(Cmat + (size_t)r * Cn + col) = make_float2(c0, c1);
            if (r + 8 < mlim)
                *(float2*)(Cmat + (size_t)(r + 8) * Cn + col) = make_float2(c2, c3);
        }
    }
}

// ---------------- fused Q + K + V projections: one launch fills the chip ----------------
// blocks [0, 252): Q tiles (63 m-tiles x 4 n-tiles, 128x128)
// blocks [252, 316): KV tiles (4 n-tiles x 8 batches x {K,V}, 64x128)
__global__ void __launch_bounds__(256) k_qkv(const float* __restrict__ bq_,
                                             const float* __restrict__ bk_,
                                             const float* __restrict__ bv_)
{
    const int bid = blockIdx.x;
    if (bid < 252) {
        const int mt = bid >> 2, nt = bid & 3;
        gemm_body<128,128,true>(g_xn, g_wq, bq_, g_q, mt * 128, nt * 128, MTOK);
    } else {
        const int r  = bid - 252;           // 0..63
        const int nt = r & 3;
        const int b  = (r >> 2) & 7;
        const int m0 = b * Sn;              // first KEEP=64 tokens of batch b
        if (r < 32) gemm_body<64,128,true>(g_xn, g_wk, bk_, g_k, m0, nt * 128, MTOK);
        else        gemm_body<64,128,true>(g_xn, g_wv, bv_, g_v, m0, nt * 128, MTOK);
    }
}

__global__ void __launch_bounds__(256) k_gemm_out(const float* __restrict__ bias,
                                                  float* __restrict__ out)
{
    const int mt = blockIdx.x >> 2, nt = blockIdx.x & 3;
    gemm_body<128,128,false>(g_ctx, g_wo, bias, out, mt * 128, nt * 128, MTOK);
}

// ---------------- tensor-core attention (R7-proven, cvt-free loads) ----------------
// Per block: one (b,h), 64 queries, 64 keys. S = Q@K^T (tf32 MMA);
// branchless p = exp(0.125*s - j) (static-max: score-iq = qk*scale - j, iq drops out
// of softmax); row sums in registers via quad shuffles; P overwrites the warp's own
// Q rows; ctx = P@V with V in natural [key][dim] layout. Inputs are pre-rounded tf32.
__global__ void __launch_bounds__(128) k_attn()
{
    const int qt  = blockIdx.x;        // 0..15 (64 queries each; last partially valid)
    const int bh  = blockIdx.y;
    const int b   = bh >> 3;
    const int h   = bh & 7;
    const int tid = threadIdx.x;
    const int warp = tid >> 5, lane = tid & 31;
    const int g = lane >> 2, tig = lane & 3;
    const int wm = warp * 16;

    __shared__ uint32_t Qs[64*64];     // [q][dim] tf32 bits; later reused as P [q][key]
    __shared__ uint32_t Ks[64*64];     // [key][dim]
    __shared__ uint32_t Vs[64*64];     // [key][dim]

    // cooperative loads (raw tf32 bits, swizzled uint4 stores)
    {
        const int c  = (tid & 15) * 4;
        const int r0 = tid >> 4;
        for (int r = r0; r < 64; r += 8) {
            const size_t kb = ((size_t)(b * Sn + r)) * Cn + h * Dn + c;
            *(uint4*)&Ks[swz64(r, c)] = *(const uint4*)(g_k + kb);
            *(uint4*)&Vs[swz64(r, c)] = *(const uint4*)(g_v + kb);
            int qr = qt * 64 + r; if (qr > Sn - 1) qr = Sn - 1;
            *(uint4*)&Qs[swz64(r, c)] = *(const uint4*)(g_q + ((size_t)(b * Sn + qr)) * Cn + h * Dn + c);
        }
    }
    __syncthreads();

    // S = Q @ K^T : warp covers 16 q-rows x 64 keys (8 n8 tiles), contraction k=64
    float acc[8][4];
#pragma unroll
    for (int ni = 0; ni < 8; ni++)
#pragma unroll
        for (int t = 0; t < 4; t++) acc[ni][t] = 0.0f;

#pragma unroll
    for (int ks = 0; ks < 8; ks++) {
        const int k0 = ks * 8;
        uint32_t a[4];
        a[0] = Qs[swz64(wm + g,     k0 + tig)];
        a[1] = Qs[swz64(wm + g + 8, k0 + tig)];
        a[2] = Qs[swz64(wm + g,     k0 + tig + 4)];
        a[3] = Qs[swz64(wm + g + 8, k0 + tig + 4)];
#pragma unroll
        for (int ni = 0; ni < 8; ni++)
            mma_tf32(acc[ni], a, Ks[swz64(ni*8 + g, k0 + tig)], Ks[swz64(ni*8 + g, k0 + tig + 4)]);
    }

    __syncwarp();   // all lanes done reading this warp's Q rows before P overwrites them

    // P = exp(0.125*s - j) rounded to tf32; row sums over the rounded values
    float rs0 = 0.0f, rs1 = 0.0f;
#pragma unroll
    for (int ni = 0; ni < 8; ni++) {
        const float j0 = (float)(ni*8 + 2*tig);
        const float p0 = rnd_tf32(__expf(fmaf(acc[ni][0], 0.125f, -j0)));
        const float p1 = rnd_tf32(__expf(fmaf(acc[ni][1], 0.125f, -(j0 + 1.0f))));
        const float p2 = rnd_tf32(__expf(fmaf(acc[ni][2], 0.125f, -j0)));
        const float p3 = rnd_tf32(__expf(fmaf(acc[ni][3], 0.125f, -(j0 + 1.0f))));
        rs0 += p0 + p1;
        rs1 += p2 + p3;
        *(uint2*)&Qs[swz64(wm + g,     ni*8 + 2*tig)] = make_uint2(__float_as_uint(p0), __float_as_uint(p1));
        *(uint2*)&Qs[swz64(wm + g + 8, ni*8 + 2*tig)] = make_uint2(__float_as_uint(p2), __float_as_uint(p3));
    }
    rs0 += __shfl_xor_sync(0xffffffffu, rs0, 1);
    rs0 += __shfl_xor_sync(0xffffffffu, rs0, 2);
    rs1 += __shfl_xor_sync(0xffffffffu, rs1, 1);
    rs1 += __shfl_xor_sync(0xffffffffu, rs1, 2);

    __syncwarp();   // P writes visible within the warp

    // ctx = P @ V : A = P [q][key], B = V [key][dim]
    float acc2[8][4];
#pragma unroll
    for (int ni = 0; ni < 8; ni++)
#pragma unroll
        for (int t = 0; t < 4; t++) acc2[ni][t] = 0.0f;

#pragma unroll
    for (int ks = 0; ks < 8; ks++) {
        const int k0 = ks * 8;
        uint32_t a[4];
        a[0] = Qs[swz64(wm + g,     k0 + tig)];
        a[1] = Qs[swz64(wm + g + 8, k0 + tig)];
        a[2] = Qs[swz64(wm + g,     k0 + tig + 4)];
        a[3] = Qs[swz64(wm + g + 8, k0 + tig + 4)];
#pragma unroll
        for (int ni = 0; ni < 8; ni++)
            mma_tf32(acc2[ni], a, Vs[swz64(k0 + tig, ni*8 + g)], Vs[swz64(k0 + tig + 4, ni*8 + g)]);
    }

    // epilogue: normalize, round to tf32 (feeds the out-GEMM raw), write
    const int   q0  = qt * 64 + wm + g;
    const int   q1  = q0 + 8;
    const float il0 = 1.0f / rs0;
    const float il1 = 1.0f / rs1;
#pragma unroll
    for (int ni = 0; ni < 8; ni++) {
        const int d = ni*8 + 2*tig;
        if (q0 < Sn)
            *(float2*)(g_ctx + ((size_t)(b * Sn + q0)) * Cn + h * Dn + d) =
                make_float2(rnd_tf32(acc2[ni][0] * il0), rnd_tf32(acc2[ni][1] * il0));
        if (q1 < Sn)
            *(float2*)(g_ctx + ((size_t)(b * Sn + q1)) * Cn + h * Dn + d) =
                make_float2(rnd_tf32(acc2[ni][2] * il1), rnd_tf32(acc2[ni][3] * il1));
    }
}

// ---------------- launch ----------------
extern "C" void kernel_launch(void* const* d_in, const int* in_sizes, int n_in,
                              void* d_out, int out_size)
{
    const float* x   = (const float*)d_in[0];
    const float* lng = (const float*)d_in[1] + LAYER * Cn;
    const float* lnb = (const float*)d_in[2] + LAYER * Cn;
    const float* Wq  = (const float*)d_in[3] + (size_t)LAYER * Cn * Cn;
    const float* bq  = (const float*)d_in[4] + LAYER * Cn;
    const float* Wk  = (const float*)d_in[5] + (size_t)LAYER * Cn * Cn;
    const float* bk  = (const float*)d_in[6] + LAYER * Cn;
    const float* Wv  = (const float*)d_in[7] + (size_t)LAYER * Cn * Cn;
    const float* bv  = (const float*)d_in[8] + LAYER * Cn;
    const float* Wo  = (const float*)d_in[9] + (size_t)LAYER * Cn * Cn;
    const float* bo  = (const float*)d_in[10] + LAYER * Cn;
    float* out = (float*)d_out;

    const int smem_gemm = 2 * (128 + 128) * 20 * 4;   // 40960 bytes (128x128 tiles)

    k_pre     <<<LN_BLOCKS + 1024, 256>>>(x, lng, lnb, Wq, Wk, Wv, Wo);
    k_qkv     <<<316, 256, smem_gemm>>>(bq, bk, bv);
    k_attn    <<<dim3(16, 64), 128>>>();
    k_gemm_out<<<252, 256, smem_gemm>>>(bo, out);
}